// round 15
// baseline (speedup 1.0000x reference)
#include <cuda_runtime.h>
#include <math.h>

#define NN   100000
#define EE   1600000
#define NSG2 20000
#define NSG  2000
#define NGR  64
#define NTILE 1563   // ceil(NN/64)
#define SCT  512

typedef unsigned long long ull;

// ---------------- scratch ----------------
__device__ float g_x [NN * 64];
__device__ float g_m [NN * 64];
__device__ float g_wf[5 * 64 * 192];   // fused Wc @ Wih per layer
__device__ float g_s2 [NSG2 * 64];
__device__ float g_s2b[NSG2 * 64];
__device__ float g_s1 [NSG * 64];
__device__ float g_s1b[NSG * 64];
__device__ float g_gg [NGR * 64];
__device__ int   g_rowptr[NN + 1];
__device__ int   g_cursor[NN];
__device__ int   g_colx[EE];

// ---------------- packed f32x2 helpers ----------------
__device__ __forceinline__ ull ffma2(ull a, ull b, ull c) {
    ull d;
    asm("fma.rn.f32x2 %0, %1, %2, %3;" : "=l"(d) : "l"(a), "l"(b), "l"(c));
    return d;
}
__device__ __forceinline__ ull addf2(ull a, ull b) {
    ull d;
    asm("add.rn.f32x2 %0, %1, %2;" : "=l"(d) : "l"(a), "l"(b));
    return d;
}
__device__ __forceinline__ float accred(ull u) {
    return __uint_as_float((unsigned)u) + __uint_as_float((unsigned)(u >> 32));
}
__device__ __forceinline__ ull packf2(float lo, float hi) {
    return ((ull)__float_as_uint(hi) << 32) | (ull)__float_as_uint(lo);
}
__device__ __forceinline__ float sigm(float v) { return 1.f / (1.f + __expf(-v)); }

__device__ __forceinline__ void fma_row8(ull a, const ulonglong2& w0, const ulonglong2& w1,
                                         const ulonglong2& w2, const ulonglong2& w3, ull* acc) {
    acc[0] = ffma2(a, w0.x, acc[0]); acc[1] = ffma2(a, w0.y, acc[1]);
    acc[2] = ffma2(a, w1.x, acc[2]); acc[3] = ffma2(a, w1.y, acc[3]);
    acc[4] = ffma2(a, w2.x, acc[4]); acc[5] = ffma2(a, w2.y, acc[5]);
    acc[6] = ffma2(a, w3.x, acc[6]); acc[7] = ffma2(a, w3.y, acc[7]);
}

// ============ weight fusion: Wf[l] = conv_W[l] @ gru_Wih[l] ============
__global__ void __launch_bounds__(256) k_wfuse(const float* __restrict__ Wc,
                                               const float* __restrict__ Wih,
                                               float* __restrict__ Wf) {
    int t = blockIdx.x * 256 + threadIdx.x;
    if (t >= 5 * 64 * 192) return;
    int l = t / 12288, rem = t % 12288, k = rem / 192, c = rem % 192;
    const float* wc = Wc + l * 4096 + k * 64;
    const float* wi = Wih + l * 12288 + c;
    float s = 0.f;
#pragma unroll 8
    for (int j = 0; j < 64; j++) s += wc[j] * wi[j * 192];
    Wf[t] = s;
}

// ============ embed: x = zemb[z0] + zemb[z1] ============
__global__ void __launch_bounds__(256) k_embed(const int* __restrict__ z,
                                               const float* __restrict__ zemb,
                                               float* __restrict__ gx) {
    int t = blockIdx.x * 256 + threadIdx.x;
    int n = t >> 4, c = t & 15;
    if (n >= NN) return;
    int2 zz = ((const int2*)z)[n];
    float4 a = ((const float4*)(zemb + zz.x * 64))[c];
    float4 b = ((const float4*)(zemb + zz.y * 64))[c];
    ((float4*)gx)[n * 16 + c] = make_float4(a.x + b.x, a.y + b.y, a.z + b.z, a.w + b.w);
}

// ===== transform (persistent, 128 thr, two-phase K, in-place): x=[x,ze]@Wt+bt =====
__global__ void __launch_bounds__(128, 4) k_transform(const int* __restrict__ z,
                                                      const float* __restrict__ zemb,
                                                      const float* __restrict__ Wt,
                                                      const float* __restrict__ bt,
                                                      float* __restrict__ gx) {
    extern __shared__ ull sm[];
    ull* in_s = sm;            // 64 x 33 = 2112
    ull* wt_s = sm + 2112;     // 4096   -> 6208 ull = 49664 B
    int tid = threadIdx.x;

    for (int idx = tid; idx < 4096; idx += 128) {
        int kp = idx >> 6, c = idx & 63;
        wt_s[idx] = packf2(Wt[2 * kp * 64 + c], Wt[(2 * kp + 1) * 64 + c]);
    }

    int r0 = tid & 15, ct = tid >> 4;
    float bb[8];
#pragma unroll
    for (int j = 0; j < 8; j++) bb[j] = bt[ct * 8 + j];

    for (int tile = blockIdx.x; tile < NTILE; tile += gridDim.x) {
        int node0 = tile * 64;
        __syncthreads();
        for (int idx = tid; idx < 2048; idx += 128) {
            int r = idx >> 5, kp = idx & 31;
            int gr = node0 + r;
            in_s[r * 33 + kp] = (gr < NN) ? ((const ull*)gx)[gr * 32 + kp] : 0ULL;
        }
        __syncthreads();

        ull acc[4][8];
#pragma unroll
        for (int i = 0; i < 4; i++)
#pragma unroll
            for (int j = 0; j < 8; j++) acc[i][j] = 0ULL;
#pragma unroll 4
        for (int kp = 0; kp < 32; kp++) {
            const ull* wr = wt_s + kp * 64 + ct * 8;
            ulonglong2 w0 = *(const ulonglong2*)wr;
            ulonglong2 w1 = *(const ulonglong2*)(wr + 2);
            ulonglong2 w2 = *(const ulonglong2*)(wr + 4);
            ulonglong2 w3 = *(const ulonglong2*)(wr + 6);
#pragma unroll
            for (int i = 0; i < 4; i++)
                fma_row8(in_s[(r0 + 16 * i) * 33 + kp], w0, w1, w2, w3, acc[i]);
        }
        __syncthreads();
        for (int idx = tid; idx < 2048; idx += 128) {
            int r = idx >> 5, kp = idx & 31;
            int gr = node0 + r;
            ull v = 0;
            if (gr < NN) {
                int2 zz = ((const int2*)z)[gr];
                float2 a = *(const float2*)(zemb + zz.x * 64 + 2 * kp);
                float2 b = *(const float2*)(zemb + zz.y * 64 + 2 * kp);
                v = packf2(a.x + b.x, a.y + b.y);
            }
            in_s[r * 33 + kp] = v;
        }
        __syncthreads();
#pragma unroll 4
        for (int kp = 32; kp < 64; kp++) {
            const ull* wr = wt_s + kp * 64 + ct * 8;
            ulonglong2 w0 = *(const ulonglong2*)wr;
            ulonglong2 w1 = *(const ulonglong2*)(wr + 2);
            ulonglong2 w2 = *(const ulonglong2*)(wr + 4);
            ulonglong2 w3 = *(const ulonglong2*)(wr + 6);
#pragma unroll
            for (int i = 0; i < 4; i++)
                fma_row8(in_s[(r0 + 16 * i) * 33 + (kp - 32)], w0, w1, w2, w3, acc[i]);
        }
#pragma unroll
        for (int i = 0; i < 4; i++) {
            int gr = node0 + r0 + 16 * i;
            if (gr < NN) {
                float o[8];
#pragma unroll
                for (int j = 0; j < 8; j++) o[j] = accred(acc[i][j]) + bb[j];
                ((float4*)gx)[gr * 16 + ct * 2]     = make_float4(o[0], o[1], o[2], o[3]);
                ((float4*)gx)[gr * 16 + ct * 2 + 1] = make_float4(o[4], o[5], o[6], o[7]);
            }
        }
    }
}

// ============ gate-split fused GRU (persistent, 512 thr) — R8 verbatim ============
// gi = gm@Wf (+bih); gh = x@Whh (+bhh); h -> gx in place
__global__ void __launch_bounds__(512, 1) k_gru(const float* __restrict__ Wf,
                                                const float* __restrict__ bih,
                                                const float* __restrict__ Whh,
                                                const float* __restrict__ bhh,
                                                float* __restrict__ gx,
                                                const float* __restrict__ gm) {
    extern __shared__ ull sm[];
    ull* m_s  = sm;            // 64 x 33 = 2112
    ull* x_s  = sm + 2112;     // 2112
    ull* wi_s = sm + 4224;     // 6144
    ull* wh_s = sm + 10368;    // 6144
    float* rs = (float*)(sm + 16512);  // 64 x 65
    float* zs = rs + 4160;
    float* ns = zs + 4160;             // 22752 ull = 182016 B
    int tid = threadIdx.x;

    for (int idx = tid; idx < 6144; idx += 512) {
        int kp = idx / 192, c = idx % 192;
        wi_s[idx] = packf2(Wf[2 * kp * 192 + c], Wf[(2 * kp + 1) * 192 + c]);
        wh_s[idx] = packf2(Whh[2 * kp * 192 + c], Whh[(2 * kp + 1) * 192 + c]);
    }

    int r0 = tid & 15, cg = tid >> 4;   // cg 0..31
    int grp = cg >> 3;                  // warp-uniform: 0=r,1=z,2=inn,3=hn
    int c8 = (cg & 7) * 8;

    for (int tile = blockIdx.x; tile < NTILE; tile += gridDim.x) {
        int node0 = tile * 64;
        __syncthreads();
        for (int idx = tid; idx < 2048; idx += 512) {
            int r = idx >> 5, kp = idx & 31;
            int gr = node0 + r;
            ull mv = 0, xv = 0;
            if (gr < NN) {
                mv = ((const ull*)gm)[gr * 32 + kp];
                xv = ((const ull*)gx)[gr * 32 + kp];
            }
            m_s[r * 33 + kp] = mv;
            x_s[r * 33 + kp] = xv;
        }
        __syncthreads();

        ull acc[4][8];
#pragma unroll
        for (int i = 0; i < 4; i++)
#pragma unroll
            for (int j = 0; j < 8; j++) acc[i][j] = 0ULL;

        if (grp == 0) {              // r = m@Wf_r + x@Whh_r
#pragma unroll 4
            for (int kp = 0; kp < 32; kp++) {
                const ull* wi = wi_s + kp * 192 + c8;
                ulonglong2 a0 = *(const ulonglong2*)wi,       a1 = *(const ulonglong2*)(wi + 2);
                ulonglong2 a2 = *(const ulonglong2*)(wi + 4), a3 = *(const ulonglong2*)(wi + 6);
#pragma unroll
                for (int i = 0; i < 4; i++)
                    fma_row8(m_s[(r0 + 16 * i) * 33 + kp], a0, a1, a2, a3, acc[i]);
                const ull* wh = wh_s + kp * 192 + c8;
                ulonglong2 b0 = *(const ulonglong2*)wh,       b1 = *(const ulonglong2*)(wh + 2);
                ulonglong2 b2 = *(const ulonglong2*)(wh + 4), b3 = *(const ulonglong2*)(wh + 6);
#pragma unroll
                for (int i = 0; i < 4; i++)
                    fma_row8(x_s[(r0 + 16 * i) * 33 + kp], b0, b1, b2, b3, acc[i]);
            }
            float bsum[8];
#pragma unroll
            for (int j = 0; j < 8; j++) bsum[j] = bih[c8 + j] + bhh[c8 + j];
#pragma unroll
            for (int i = 0; i < 4; i++) {
                int row = r0 + 16 * i;
#pragma unroll
                for (int j = 0; j < 8; j++)
                    rs[row * 65 + c8 + j] = sigm(accred(acc[i][j]) + bsum[j]);
            }
        } else if (grp == 1) {       // z
#pragma unroll 4
            for (int kp = 0; kp < 32; kp++) {
                const ull* wi = wi_s + kp * 192 + 64 + c8;
                ulonglong2 a0 = *(const ulonglong2*)wi,       a1 = *(const ulonglong2*)(wi + 2);
                ulonglong2 a2 = *(const ulonglong2*)(wi + 4), a3 = *(const ulonglong2*)(wi + 6);
#pragma unroll
                for (int i = 0; i < 4; i++)
                    fma_row8(m_s[(r0 + 16 * i) * 33 + kp], a0, a1, a2, a3, acc[i]);
                const ull* wh = wh_s + kp * 192 + 64 + c8;
                ulonglong2 b0 = *(const ulonglong2*)wh,       b1 = *(const ulonglong2*)(wh + 2);
                ulonglong2 b2 = *(const ulonglong2*)(wh + 4), b3 = *(const ulonglong2*)(wh + 6);
#pragma unroll
                for (int i = 0; i < 4; i++)
                    fma_row8(x_s[(r0 + 16 * i) * 33 + kp], b0, b1, b2, b3, acc[i]);
            }
            float bsum[8];
#pragma unroll
            for (int j = 0; j < 8; j++) bsum[j] = bih[64 + c8 + j] + bhh[64 + c8 + j];
#pragma unroll
            for (int i = 0; i < 4; i++) {
                int row = r0 + 16 * i;
#pragma unroll
                for (int j = 0; j < 8; j++)
                    zs[row * 65 + c8 + j] = sigm(accred(acc[i][j]) + bsum[j]);
            }
        } else if (grp == 2) {       // inn = m@Wf_n (held in acc)
#pragma unroll 4
            for (int kp = 0; kp < 32; kp++) {
                const ull* wi = wi_s + kp * 192 + 128 + c8;
                ulonglong2 a0 = *(const ulonglong2*)wi,       a1 = *(const ulonglong2*)(wi + 2);
                ulonglong2 a2 = *(const ulonglong2*)(wi + 4), a3 = *(const ulonglong2*)(wi + 6);
#pragma unroll
                for (int i = 0; i < 4; i++)
                    fma_row8(m_s[(r0 + 16 * i) * 33 + kp], a0, a1, a2, a3, acc[i]);
            }
        } else {                     // hn = x@Whh_n -> ns = hn + bhh
#pragma unroll 4
            for (int kp = 0; kp < 32; kp++) {
                const ull* wh = wh_s + kp * 192 + 128 + c8;
                ulonglong2 b0 = *(const ulonglong2*)wh,       b1 = *(const ulonglong2*)(wh + 2);
                ulonglong2 b2 = *(const ulonglong2*)(wh + 4), b3 = *(const ulonglong2*)(wh + 6);
#pragma unroll
                for (int i = 0; i < 4; i++)
                    fma_row8(x_s[(r0 + 16 * i) * 33 + kp], b0, b1, b2, b3, acc[i]);
            }
#pragma unroll
            for (int i = 0; i < 4; i++) {
                int row = r0 + 16 * i;
#pragma unroll
                for (int j = 0; j < 8; j++)
                    ns[row * 65 + c8 + j] = accred(acc[i][j]) + bhh[128 + c8 + j];
            }
        }
        __syncthreads();   // rs, zs, ns(hn) ready

        if (grp == 2) {    // n = tanh(inn + b + r * hn)
#pragma unroll
            for (int i = 0; i < 4; i++) {
                int row = r0 + 16 * i;
#pragma unroll
                for (int j = 0; j < 8; j++) {
                    int o = row * 65 + c8 + j;
                    ns[o] = tanhf(accred(acc[i][j]) + bih[128 + c8 + j] + rs[o] * ns[o]);
                }
            }
        }
        __syncthreads();   // ns final

        if (grp == 0) {    // out = (1-z)*n + z*x
#pragma unroll
            for (int i = 0; i < 4; i++) {
                int row = r0 + 16 * i, gr = node0 + row;
                if (gr >= NN) continue;
                float o[8];
#pragma unroll
                for (int p = 0; p < 4; p++) {
                    ull xp = x_s[row * 33 + c8 / 2 + p];
                    float xl = __uint_as_float((unsigned)xp);
                    float xh = __uint_as_float((unsigned)(xp >> 32));
                    int oo = row * 65 + c8 + 2 * p;
                    float z0 = zs[oo], z1 = zs[oo + 1];
                    o[2 * p]     = (1.f - z0) * ns[oo]     + z0 * xl;
                    o[2 * p + 1] = (1.f - z1) * ns[oo + 1] + z1 * xh;
                }
                ((float4*)gx)[gr * 16 + c8 / 4]     = make_float4(o[0], o[1], o[2], o[3]);
                ((float4*)gx)[gr * 16 + c8 / 4 + 1] = make_float4(o[4], o[5], o[6], o[7]);
            }
        }
    }
}

// ================= CSR build =================
__global__ void __launch_bounds__(256) k_hist(const int* __restrict__ ei, int* __restrict__ cnt) {
    int e = blockIdx.x * 256 + threadIdx.x;
    if (e < EE) atomicAdd(&cnt[ei[EE + e]], 1);
}
// single-block scan; converts cursor (counts) to exclusive prefix IN PLACE
__global__ void __launch_bounds__(SCT) k_scanall(int* __restrict__ cur,
                                                 int* __restrict__ rowptr) {
    __shared__ int ssum[SCT];
    int t = threadIdx.x;
    const int CH = (NN + SCT - 1) / SCT;
    int beg = t * CH, end = beg + CH > NN ? NN : beg + CH;
    int s = 0;
    for (int i = beg; i < end; i++) s += cur[i];
    ssum[t] = s;
    __syncthreads();
    for (int off = 1; off < SCT; off <<= 1) {
        int a = (t >= off) ? ssum[t - off] : 0;
        __syncthreads();
        ssum[t] += a;
        __syncthreads();
    }
    int run = (t > 0) ? ssum[t - 1] : 0;
    for (int i = beg; i < end; i++) {
        int c = cur[i];
        cur[i] = run;          // exclusive prefix -> fill cursor
        run += c;
        rowptr[i + 1] = run;   // inclusive prefix
    }
    if (t == 0) rowptr[0] = 0;
}
__global__ void __launch_bounds__(256) k_fill(const int* __restrict__ ei,
                                              int* __restrict__ cursor, int* __restrict__ colx) {
    int e = blockIdx.x * 256 + threadIdx.x;
    if (e >= EE) return;
    int pos = atomicAdd(&cursor[ei[EE + e]], 1);
    colx[pos] = ei[e];
}

// ================= gather: gm[n] = sum_{e in CSR[n]} x[col[e]] =================
__global__ void __launch_bounds__(256) k_gather(const int* __restrict__ rowptr,
                                                const int* __restrict__ colx,
                                                const float* __restrict__ gx,
                                                float* __restrict__ gm) {
    int w = (blockIdx.x * 256 + threadIdx.x) >> 5;
    int lane = threadIdx.x & 31;
    if (w >= NN) return;
    int s = rowptr[w], e = rowptr[w + 1];
    const ull* X = (const ull*)gx;
    ull a0 = 0, a1 = 0, a2 = 0, a3 = 0;
    int i = s;
    for (; i + 3 < e; i += 4) {
        int c0 = colx[i], c1 = colx[i + 1], c2 = colx[i + 2], c3 = colx[i + 3];
        a0 = addf2(a0, X[(size_t)c0 * 32 + lane]);
        a1 = addf2(a1, X[(size_t)c1 * 32 + lane]);
        a2 = addf2(a2, X[(size_t)c2 * 32 + lane]);
        a3 = addf2(a3, X[(size_t)c3 * 32 + lane]);
    }
    for (; i < e; i++) a0 = addf2(a0, X[(size_t)colx[i] * 32 + lane]);
    a0 = addf2(addf2(a0, a1), addf2(a2, a3));
    ((ull*)gm)[(size_t)w * 32 + lane] = a0;
}

// ================= segment sum (pooling) =================
__global__ void __launch_bounds__(256) k_segsum(const float* __restrict__ src,
                                                float* __restrict__ dst,
                                                const int* __restrict__ map, int R) {
    long long t = (long long)blockIdx.x * 256 + threadIdx.x;
    int r = (int)(t >> 2);
    if (r >= R) return;
    int q = (int)(t & 3);
    int s = map[r];
    const float4* sp = (const float4*)(src + r * 64) + q * 4;
    float* dp = dst + s * 64 + q * 16;
#pragma unroll
    for (int i = 0; i < 4; i++) {
        float4 v = sp[i];
        asm volatile("red.global.add.v4.f32 [%0], {%1,%2,%3,%4};"
                     :: "l"(dp + i * 4), "f"(v.x), "f"(v.y), "f"(v.z), "f"(v.w)
                     : "memory");
    }
}

// ================= 2-layer MLP =================
__device__ __forceinline__ void zero_acc(ull acc[4][4]) {
#pragma unroll
    for (int i = 0; i < 4; i++)
#pragma unroll
        for (int j = 0; j < 4; j++) acc[i][j] = 0ULL;
}
__device__ __forceinline__ void load_wpack(ull* wp, const float* __restrict__ W,
                                           int ldw, int coff, int K2, int tid) {
    for (int idx = tid; idx < K2 * 64; idx += 256) {
        int kp = idx >> 6, j = idx & 63;
        wp[idx] = packf2(W[(2 * kp) * ldw + coff + j],
                         W[(2 * kp + 1) * ldw + coff + j]);
    }
}
template <int K2>
__device__ __forceinline__ void gemm_acc(const ull* __restrict__ in_s,
                                         const ull* __restrict__ wp_s,
                                         ull acc[4][4], int nt, int ct) {
#pragma unroll 8
    for (int kp = 0; kp < K2; kp++) {
        ulonglong2 w01 = *(const ulonglong2*)(wp_s + kp * 64 + ct * 4);
        ulonglong2 w23 = *(const ulonglong2*)(wp_s + kp * 64 + ct * 4 + 2);
#pragma unroll
        for (int i = 0; i < 4; i++) {
            ull a = in_s[(nt + 16 * i) * K2 + kp];
            acc[i][0] = ffma2(a, w01.x, acc[i][0]);
            acc[i][1] = ffma2(a, w01.y, acc[i][1]);
            acc[i][2] = ffma2(a, w23.x, acc[i][2]);
            acc[i][3] = ffma2(a, w23.y, acc[i][3]);
        }
    }
}
__global__ void __launch_bounds__(256) k_mlp(const float* __restrict__ in,
                                             float* __restrict__ out, int R,
                                             const float* __restrict__ W1,
                                             const float* __restrict__ b1,
                                             const float* __restrict__ W2,
                                             const float* __restrict__ b2) {
    extern __shared__ ull sm[];
    ull* in_s  = sm;
    ull* w1_s  = sm + 2048;
    ull* mid_s = sm + 4096;
    ull* w2_s  = sm + 6144;
    int tid = threadIdx.x;
    int row0 = blockIdx.x * 64;

    for (int idx = tid; idx < 1024; idx += 256) {
        int r = idx >> 4, c = idx & 15;
        int gr = row0 + r;
        float4 v = (gr < R) ? ((const float4*)in)[gr * 16 + c]
                            : make_float4(0.f, 0.f, 0.f, 0.f);
        ((float4*)in_s)[r * 16 + c] = v;
    }
    load_wpack(w1_s, W1, 64, 0, 32, tid);
    load_wpack(w2_s, W2, 64, 0, 32, tid);
    __syncthreads();

    int nt = tid >> 4, ct = tid & 15;
    ull acc[4][4];
    zero_acc(acc);
    gemm_acc<32>(in_s, w1_s, acc, nt, ct);
    float a0 = b1[ct * 4], a1 = b1[ct * 4 + 1], a2 = b1[ct * 4 + 2], a3 = b1[ct * 4 + 3];
#pragma unroll
    for (int i = 0; i < 4; i++) {
        int node = nt + 16 * i;
        float o0 = fmaxf(accred(acc[i][0]) + a0, 0.f);
        float o1 = fmaxf(accred(acc[i][1]) + a1, 0.f);
        float o2 = fmaxf(accred(acc[i][2]) + a2, 0.f);
        float o3 = fmaxf(accred(acc[i][3]) + a3, 0.f);
        mid_s[node * 32 + ct * 2]     = packf2(o0, o1);
        mid_s[node * 32 + ct * 2 + 1] = packf2(o2, o3);
    }
    __syncthreads();
    zero_acc(acc);
    gemm_acc<32>(mid_s, w2_s, acc, nt, ct);
    float c0b = b2[ct * 4], c1b = b2[ct * 4 + 1], c2b = b2[ct * 4 + 2], c3b = b2[ct * 4 + 3];
#pragma unroll
    for (int i = 0; i < 4; i++) {
        int gr = row0 + nt + 16 * i;
        if (gr < R)
            ((float4*)out)[gr * 16 + ct] = make_float4(
                accred(acc[i][0]) + c0b, accred(acc[i][1]) + c1b,
                accred(acc[i][2]) + c2b, accred(acc[i][3]) + c3b);
    }
}

// ================= final head =================
__device__ __forceinline__ float elu1(float v) { return v > 0.f ? v : expm1f(v); }

__global__ void k_final(const float* __restrict__ g,
                        const float* __restrict__ W1, const float* __restrict__ b1,
                        const float* __restrict__ W2, const float* __restrict__ b2,
                        const float* __restrict__ W3, const float* __restrict__ b3,
                        float* __restrict__ out) {
    int i = threadIdx.x;
    if (i >= NGR) return;
    float xr[64];
#pragma unroll
    for (int k = 0; k < 64; k++) xr[k] = g[i * 64 + k];
    float a1[32];
#pragma unroll
    for (int j = 0; j < 32; j++) {
        float s = b1[j];
#pragma unroll
        for (int k = 0; k < 64; k++) s += xr[k] * W1[k * 32 + j];
        a1[j] = elu1(s);
    }
    float a2[16];
#pragma unroll
    for (int j = 0; j < 16; j++) {
        float s = b2[j];
#pragma unroll
        for (int k = 0; k < 32; k++) s += a1[k] * W2[k * 16 + j];
        a2[j] = elu1(s);
    }
    float o = b3[0];
#pragma unroll
    for (int k = 0; k < 16; k++) o += a2[k] * W3[k];
    out[i] = o;
}

// ================= host launcher =================
extern "C" void kernel_launch(void* const* d_in, const int* in_sizes, int n_in,
                              void* d_out, int out_size) {
    (void)in_sizes; (void)n_in; (void)out_size;
    const int*   z       = (const int*)d_in[0];
    const int*   ei      = (const int*)d_in[1];
    const int*   n2s2    = (const int*)d_in[2];
    const int*   s22s    = (const int*)d_in[3];
    const int*   s2g     = (const int*)d_in[4];
    const float* z_emb   = (const float*)d_in[5];
    const float* trans_W = (const float*)d_in[6];
    const float* trans_b = (const float*)d_in[7];
    const float* conv_W  = (const float*)d_in[8];
    const float* Wih     = (const float*)d_in[9];
    const float* bih     = (const float*)d_in[10];
    const float* Whh     = (const float*)d_in[11];
    const float* bhh     = (const float*)d_in[12];
    const float* epW1 = (const float*)d_in[13]; const float* epb1 = (const float*)d_in[14];
    const float* epW2 = (const float*)d_in[15]; const float* epb2 = (const float*)d_in[16];
    const float* npW1 = (const float*)d_in[17]; const float* npb1 = (const float*)d_in[18];
    const float* npW2 = (const float*)d_in[19]; const float* npb2 = (const float*)d_in[20];
    const float* fc1W = (const float*)d_in[21]; const float* fc1b = (const float*)d_in[22];
    const float* fc2W = (const float*)d_in[23]; const float* fc2b = (const float*)d_in[24];
    const float* fc3W = (const float*)d_in[25]; const float* fc3b = (const float*)d_in[26];

    float *gx, *gm, *gwf, *gs2, *gs2b, *gs1, *gs1b, *gg;
    int *rowptr, *cursor, *colx;
    cudaGetSymbolAddress((void**)&gx,     g_x);
    cudaGetSymbolAddress((void**)&gm,     g_m);
    cudaGetSymbolAddress((void**)&gwf,    g_wf);
    cudaGetSymbolAddress((void**)&gs2,    g_s2);
    cudaGetSymbolAddress((void**)&gs2b,   g_s2b);
    cudaGetSymbolAddress((void**)&gs1,    g_s1);
    cudaGetSymbolAddress((void**)&gs1b,   g_s1b);
    cudaGetSymbolAddress((void**)&gg,     g_gg);
    cudaGetSymbolAddress((void**)&rowptr, g_rowptr);
    cudaGetSymbolAddress((void**)&cursor, g_cursor);
    cudaGetSymbolAddress((void**)&colx,   g_colx);

    static int attr_done = 0;
    if (!attr_done) {
        cudaFuncSetAttribute(k_transform, cudaFuncAttributeMaxDynamicSharedMemorySize, 50176);
        cudaFuncSetAttribute(k_gru,       cudaFuncAttributeMaxDynamicSharedMemorySize, 182272);
        cudaFuncSetAttribute(k_mlp,       cudaFuncAttributeMaxDynamicSharedMemorySize, 65536);
        attr_done = 1;
    }

    // ---- weight fusion + CSR build (once per call) ----
    k_wfuse<<<(5 * 64 * 192 + 255) / 256, 256>>>(conv_W, Wih, gwf);
    cudaMemsetAsync(cursor, 0, (size_t)NN * 4);
    k_hist<<<(EE + 255) / 256, 256>>>(ei, cursor);
    k_scanall<<<1, SCT>>>(cursor, rowptr);
    k_fill<<<(EE + 255) / 256, 256>>>(ei, cursor, colx);

    const int GGRID = 148;
    int gath_blocks = (NN * 32 + 255) / 256;

    // layer 0
    k_embed<<<(NN * 16 + 255) / 256, 256>>>(z, z_emb, gx);
    k_gather<<<gath_blocks, 256>>>(rowptr, colx, gx, gm);
    k_gru<<<GGRID, 512, 182272>>>(gwf, bih, Whh, bhh, gx, gm);

    // layers 1..4
    for (int l = 1; l < 5; l++) {
        k_transform<<<4 * GGRID, 128, 50176>>>(z, z_emb + (size_t)l * 100 * 64,
                                               trans_W + (size_t)(l - 1) * 128 * 64,
                                               trans_b + (size_t)(l - 1) * 64, gx);
        k_gather<<<gath_blocks, 256>>>(rowptr, colx, gx, gm);
        k_gru<<<GGRID, 512, 182272>>>(gwf + (size_t)l * 12288, bih + (size_t)l * 192,
                                      Whh + (size_t)l * 64 * 192, bhh + (size_t)l * 192,
                                      gx, gm);
    }

    // pooling + MLPs
    cudaMemsetAsync(gs2, 0, (size_t)NSG2 * 64 * 4);
    k_segsum<<<(NN * 4 + 255) / 256, 256>>>(gx, gs2, n2s2, NN);
    k_mlp<<<(NSG2 + 63) / 64, 256, 65536>>>(gs2, gs2b, NSG2, epW1, epb1, epW2, epb2);

    cudaMemsetAsync(gs1, 0, (size_t)NSG * 64 * 4);
    k_segsum<<<(NSG2 * 4 + 255) / 256, 256>>>(gs2b, gs1, s22s, NSG2);
    k_mlp<<<(NSG + 63) / 64, 256, 65536>>>(gs1, gs1b, NSG, npW1, npb1, npW2, npb2);

    cudaMemsetAsync(gg, 0, (size_t)NGR * 64 * 4);
    k_segsum<<<(NSG * 4 + 255) / 256, 256>>>(gs1b, gg, s2g, NSG);

    k_final<<<1, 64>>>(gg, fc1W, fc1b, fc2W, fc2b, fc3W, fc3b, (float*)d_out);
}

// round 16
// speedup vs baseline: 1.1541x; 1.1541x over previous
#include <cuda_runtime.h>
#include <math.h>

#define NN   100000
#define EE   1600000
#define NSG2 20000
#define NSG  2000
#define NGR  64
#define NTILE 1563   // ceil(NN/64)
#define SCB  512
#define NB   196     // ceil(NN/SCB)

typedef unsigned long long ull;

// ---------------- scratch ----------------
__device__ float g_x [NN * 64];
__device__ float g_m [NN * 64];
__device__ float g_wf[5 * 64 * 192];   // fused Wc @ Wih per layer
__device__ float g_s2 [NSG2 * 64];
__device__ float g_s2b[NSG2 * 64];
__device__ float g_s1 [NSG * 64];
__device__ float g_s1b[NSG * 64];
__device__ float g_gg [NGR * 64];
__device__ int   g_rowptr[NN + 1];
__device__ int   g_cursor[NN];
__device__ int   g_colx[EE];
__device__ int   g_bsum[SCB];

// ---------------- packed f32x2 helpers ----------------
__device__ __forceinline__ ull ffma2(ull a, ull b, ull c) {
    ull d;
    asm("fma.rn.f32x2 %0, %1, %2, %3;" : "=l"(d) : "l"(a), "l"(b), "l"(c));
    return d;
}
__device__ __forceinline__ ull addf2(ull a, ull b) {
    ull d;
    asm("add.rn.f32x2 %0, %1, %2;" : "=l"(d) : "l"(a), "l"(b));
    return d;
}
__device__ __forceinline__ float accred(ull u) {
    return __uint_as_float((unsigned)u) + __uint_as_float((unsigned)(u >> 32));
}
__device__ __forceinline__ ull packf2(float lo, float hi) {
    return ((ull)__float_as_uint(hi) << 32) | (ull)__float_as_uint(lo);
}
__device__ __forceinline__ float sigm(float v) { return 1.f / (1.f + __expf(-v)); }

__device__ __forceinline__ void fma_row8(ull a, const ulonglong2& w0, const ulonglong2& w1,
                                         const ulonglong2& w2, const ulonglong2& w3, ull* acc) {
    acc[0] = ffma2(a, w0.x, acc[0]); acc[1] = ffma2(a, w0.y, acc[1]);
    acc[2] = ffma2(a, w1.x, acc[2]); acc[3] = ffma2(a, w1.y, acc[3]);
    acc[4] = ffma2(a, w2.x, acc[4]); acc[5] = ffma2(a, w2.y, acc[5]);
    acc[6] = ffma2(a, w3.x, acc[6]); acc[7] = ffma2(a, w3.y, acc[7]);
}

// ============ weight fusion: Wf[l] = conv_W[l] @ gru_Wih[l] ============
__global__ void __launch_bounds__(256) k_wfuse(const float* __restrict__ Wc,
                                               const float* __restrict__ Wih,
                                               float* __restrict__ Wf) {
    int t = blockIdx.x * 256 + threadIdx.x;
    if (t >= 5 * 64 * 192) return;
    int l = t / 12288, rem = t % 12288, k = rem / 192, c = rem % 192;
    const float* wc = Wc + l * 4096 + k * 64;
    const float* wi = Wih + l * 12288 + c;
    float s = 0.f;
#pragma unroll 8
    for (int j = 0; j < 64; j++) s += wc[j] * wi[j * 192];
    Wf[t] = s;
}

// ============ embed: x = zemb[z0] + zemb[z1] ============
__global__ void __launch_bounds__(256) k_embed(const int* __restrict__ z,
                                               const float* __restrict__ zemb,
                                               float* __restrict__ gx) {
    int t = blockIdx.x * 256 + threadIdx.x;
    int n = t >> 4, c = t & 15;
    if (n >= NN) return;
    int2 zz = ((const int2*)z)[n];
    float4 a = ((const float4*)(zemb + zz.x * 64))[c];
    float4 b = ((const float4*)(zemb + zz.y * 64))[c];
    ((float4*)gx)[n * 16 + c] = make_float4(a.x + b.x, a.y + b.y, a.z + b.z, a.w + b.w);
}

// ===== transform (persistent, 128 thr, two-phase K, 4 rows x 8 cols): x=[x,ze]@Wt+bt =====
__global__ void __launch_bounds__(128, 4) k_transform(const int* __restrict__ z,
                                                      const float* __restrict__ zemb,
                                                      const float* __restrict__ Wt,
                                                      const float* __restrict__ bt,
                                                      float* __restrict__ gx) {
    extern __shared__ ull sm[];
    ull* in_s = sm;            // 64 x 33 = 2112
    ull* wt_s = sm + 2112;     // 64 x 64 = 4096   -> 6208 ull = 49664 B
    int tid = threadIdx.x;

    for (int idx = tid; idx < 4096; idx += 128) {
        int kp = idx >> 6, c = idx & 63;
        wt_s[idx] = packf2(Wt[2 * kp * 64 + c], Wt[(2 * kp + 1) * 64 + c]);
    }

    int r0 = tid & 15, ct = tid >> 4;
    float bb[8];
#pragma unroll
    for (int j = 0; j < 8; j++) bb[j] = bt[ct * 8 + j];

    for (int tile = blockIdx.x; tile < NTILE; tile += gridDim.x) {
        int node0 = tile * 64;
        __syncthreads();   // weights ready / prev iter reads done
        // phase 1: x
        for (int idx = tid; idx < 2048; idx += 128) {
            int r = idx >> 5, kp = idx & 31;
            int gr = node0 + r;
            in_s[r * 33 + kp] = (gr < NN) ? ((const ull*)gx)[gr * 32 + kp] : 0ULL;
        }
        __syncthreads();

        ull acc[4][8];
#pragma unroll
        for (int i = 0; i < 4; i++)
#pragma unroll
            for (int j = 0; j < 8; j++) acc[i][j] = 0ULL;
#pragma unroll 4
        for (int kp = 0; kp < 32; kp++) {
            const ull* wr = wt_s + kp * 64 + ct * 8;
            ulonglong2 w0 = *(const ulonglong2*)wr;
            ulonglong2 w1 = *(const ulonglong2*)(wr + 2);
            ulonglong2 w2 = *(const ulonglong2*)(wr + 4);
            ulonglong2 w3 = *(const ulonglong2*)(wr + 6);
#pragma unroll
            for (int i = 0; i < 4; i++)
                fma_row8(in_s[(r0 + 16 * i) * 33 + kp], w0, w1, w2, w3, acc[i]);
        }
        __syncthreads();
        // phase 2: ze
        for (int idx = tid; idx < 2048; idx += 128) {
            int r = idx >> 5, kp = idx & 31;
            int gr = node0 + r;
            ull v = 0;
            if (gr < NN) {
                int2 zz = ((const int2*)z)[gr];
                float2 a = *(const float2*)(zemb + zz.x * 64 + 2 * kp);
                float2 b = *(const float2*)(zemb + zz.y * 64 + 2 * kp);
                v = packf2(a.x + b.x, a.y + b.y);
            }
            in_s[r * 33 + kp] = v;
        }
        __syncthreads();
#pragma unroll 4
        for (int kp = 32; kp < 64; kp++) {
            const ull* wr = wt_s + kp * 64 + ct * 8;
            ulonglong2 w0 = *(const ulonglong2*)wr;
            ulonglong2 w1 = *(const ulonglong2*)(wr + 2);
            ulonglong2 w2 = *(const ulonglong2*)(wr + 4);
            ulonglong2 w3 = *(const ulonglong2*)(wr + 6);
#pragma unroll
            for (int i = 0; i < 4; i++)
                fma_row8(in_s[(r0 + 16 * i) * 33 + (kp - 32)], w0, w1, w2, w3, acc[i]);
        }
        // write x
#pragma unroll
        for (int i = 0; i < 4; i++) {
            int gr = node0 + r0 + 16 * i;
            if (gr < NN) {
                float o[8];
#pragma unroll
                for (int j = 0; j < 8; j++) o[j] = accred(acc[i][j]) + bb[j];
                ((float4*)gx)[gr * 16 + ct * 2]     = make_float4(o[0], o[1], o[2], o[3]);
                ((float4*)gx)[gr * 16 + ct * 2 + 1] = make_float4(o[4], o[5], o[6], o[7]);
            }
        }
    }
}

// ============ gate-split fused GRU (persistent, 512 thr) ============
// gi = agg @ Wf (+bih), gh = x @ Whh (+bhh); groups: 0=r, 1=z, 2=inn, 3=hn
__global__ void __launch_bounds__(512, 1) k_gru(const float* __restrict__ Wf,
                                                const float* __restrict__ bih,
                                                const float* __restrict__ Whh,
                                                const float* __restrict__ bhh,
                                                float* __restrict__ gx,
                                                const float* __restrict__ gm) {
    extern __shared__ ull sm[];
    ull* m_s  = sm;            // 64 x 33 = 2112
    ull* x_s  = sm + 2112;     // 2112
    ull* wi_s = sm + 4224;     // 32 x 192 = 6144
    ull* wh_s = sm + 10368;    // 6144
    float* rs = (float*)(sm + 16512);  // 64 x 65
    float* zs = rs + 4160;
    float* ns = zs + 4160;             // end: 22752 ull = 182016 B
    int tid = threadIdx.x;

    for (int idx = tid; idx < 6144; idx += 512) {
        int kp = idx / 192, c = idx % 192;
        wi_s[idx] = packf2(Wf[2 * kp * 192 + c], Wf[(2 * kp + 1) * 192 + c]);
        wh_s[idx] = packf2(Whh[2 * kp * 192 + c], Whh[(2 * kp + 1) * 192 + c]);
    }

    int r0 = tid & 15, cg = tid >> 4;   // cg 0..31
    int grp = cg >> 3;                  // warp-uniform
    int c8 = (cg & 7) * 8;

    for (int tile = blockIdx.x; tile < NTILE; tile += gridDim.x) {
        int node0 = tile * 64;
        __syncthreads();
        for (int idx = tid; idx < 2048; idx += 512) {
            int r = idx >> 5, kp = idx & 31;
            int gr = node0 + r;
            ull mv = 0, xv = 0;
            if (gr < NN) {
                mv = ((const ull*)gm)[gr * 32 + kp];
                xv = ((const ull*)gx)[gr * 32 + kp];
            }
            m_s[r * 33 + kp] = mv;
            x_s[r * 33 + kp] = xv;
        }
        __syncthreads();

        ull acc[4][8];
#pragma unroll
        for (int i = 0; i < 4; i++)
#pragma unroll
            for (int j = 0; j < 8; j++) acc[i][j] = 0ULL;

        if (grp == 0) {              // r = m@Wf_r + x@Whh_r
#pragma unroll 4
            for (int kp = 0; kp < 32; kp++) {
                const ull* wi = wi_s + kp * 192 + c8;
                ulonglong2 a0 = *(const ulonglong2*)wi,       a1 = *(const ulonglong2*)(wi + 2);
                ulonglong2 a2 = *(const ulonglong2*)(wi + 4), a3 = *(const ulonglong2*)(wi + 6);
#pragma unroll
                for (int i = 0; i < 4; i++)
                    fma_row8(m_s[(r0 + 16 * i) * 33 + kp], a0, a1, a2, a3, acc[i]);
                const ull* wh = wh_s + kp * 192 + c8;
                ulonglong2 b0 = *(const ulonglong2*)wh,       b1 = *(const ulonglong2*)(wh + 2);
                ulonglong2 b2 = *(const ulonglong2*)(wh + 4), b3 = *(const ulonglong2*)(wh + 6);
#pragma unroll
                for (int i = 0; i < 4; i++)
                    fma_row8(x_s[(r0 + 16 * i) * 33 + kp], b0, b1, b2, b3, acc[i]);
            }
            float bsum[8];
#pragma unroll
            for (int j = 0; j < 8; j++) bsum[j] = bih[c8 + j] + bhh[c8 + j];
#pragma unroll
            for (int i = 0; i < 4; i++) {
                int row = r0 + 16 * i;
#pragma unroll
                for (int j = 0; j < 8; j++)
                    rs[row * 65 + c8 + j] = sigm(accred(acc[i][j]) + bsum[j]);
            }
        } else if (grp == 1) {       // z
#pragma unroll 4
            for (int kp = 0; kp < 32; kp++) {
                const ull* wi = wi_s + kp * 192 + 64 + c8;
                ulonglong2 a0 = *(const ulonglong2*)wi,       a1 = *(const ulonglong2*)(wi + 2);
                ulonglong2 a2 = *(const ulonglong2*)(wi + 4), a3 = *(const ulonglong2*)(wi + 6);
#pragma unroll
                for (int i = 0; i < 4; i++)
                    fma_row8(m_s[(r0 + 16 * i) * 33 + kp], a0, a1, a2, a3, acc[i]);
                const ull* wh = wh_s + kp * 192 + 64 + c8;
                ulonglong2 b0 = *(const ulonglong2*)wh,       b1 = *(const ulonglong2*)(wh + 2);
                ulonglong2 b2 = *(const ulonglong2*)(wh + 4), b3 = *(const ulonglong2*)(wh + 6);
#pragma unroll
                for (int i = 0; i < 4; i++)
                    fma_row8(x_s[(r0 + 16 * i) * 33 + kp], b0, b1, b2, b3, acc[i]);
            }
            float bsum[8];
#pragma unroll
            for (int j = 0; j < 8; j++) bsum[j] = bih[64 + c8 + j] + bhh[64 + c8 + j];
#pragma unroll
            for (int i = 0; i < 4; i++) {
                int row = r0 + 16 * i;
#pragma unroll
                for (int j = 0; j < 8; j++)
                    zs[row * 65 + c8 + j] = sigm(accred(acc[i][j]) + bsum[j]);
            }
        } else if (grp == 2) {       // inn = m@Wf_n
#pragma unroll 4
            for (int kp = 0; kp < 32; kp++) {
                const ull* wi = wi_s + kp * 192 + 128 + c8;
                ulonglong2 a0 = *(const ulonglong2*)wi,       a1 = *(const ulonglong2*)(wi + 2);
                ulonglong2 a2 = *(const ulonglong2*)(wi + 4), a3 = *(const ulonglong2*)(wi + 6);
#pragma unroll
                for (int i = 0; i < 4; i++)
                    fma_row8(m_s[(r0 + 16 * i) * 33 + kp], a0, a1, a2, a3, acc[i]);
            }
        } else {                     // hn = x@Whh_n -> ns holds hn + bhh
#pragma unroll 4
            for (int kp = 0; kp < 32; kp++) {
                const ull* wh = wh_s + kp * 192 + 128 + c8;
                ulonglong2 b0 = *(const ulonglong2*)wh,       b1 = *(const ulonglong2*)(wh + 2);
                ulonglong2 b2 = *(const ulonglong2*)(wh + 4), b3 = *(const ulonglong2*)(wh + 6);
#pragma unroll
                for (int i = 0; i < 4; i++)
                    fma_row8(x_s[(r0 + 16 * i) * 33 + kp], b0, b1, b2, b3, acc[i]);
            }
#pragma unroll
            for (int i = 0; i < 4; i++) {
                int row = r0 + 16 * i;
#pragma unroll
                for (int j = 0; j < 8; j++)
                    ns[row * 65 + c8 + j] = accred(acc[i][j]) + bhh[128 + c8 + j];
            }
        }
        __syncthreads();   // rs, zs, ns(hn) ready

        if (grp == 2) {    // n = tanh(inn + b + r * hn)
#pragma unroll
            for (int i = 0; i < 4; i++) {
                int row = r0 + 16 * i;
#pragma unroll
                for (int j = 0; j < 8; j++) {
                    int o = row * 65 + c8 + j;
                    ns[o] = tanhf(accred(acc[i][j]) + bih[128 + c8 + j] + rs[o] * ns[o]);
                }
            }
        }
        __syncthreads();   // ns final

        if (grp == 0) {    // out = (1-z)*n + z*x
#pragma unroll
            for (int i = 0; i < 4; i++) {
                int row = r0 + 16 * i, gr = node0 + row;
                if (gr >= NN) continue;
                float o[8];
#pragma unroll
                for (int p = 0; p < 4; p++) {
                    ull xp = x_s[row * 33 + c8 / 2 + p];
                    float xl = __uint_as_float((unsigned)xp);
                    float xh = __uint_as_float((unsigned)(xp >> 32));
                    int oo = row * 65 + c8 + 2 * p;
                    float z0 = zs[oo], z1 = zs[oo + 1];
                    o[2 * p]     = (1.f - z0) * ns[oo]     + z0 * xl;
                    o[2 * p + 1] = (1.f - z1) * ns[oo + 1] + z1 * xh;
                }
                ((float4*)gx)[gr * 16 + c8 / 4]     = make_float4(o[0], o[1], o[2], o[3]);
                ((float4*)gx)[gr * 16 + c8 / 4 + 1] = make_float4(o[4], o[5], o[6], o[7]);
            }
        }
    }
}

// ================= CSR build =================
__global__ void __launch_bounds__(256) k_hist(const int* __restrict__ ei, int* __restrict__ cnt) {
    int e = blockIdx.x * 256 + threadIdx.x;
    if (e < EE) atomicAdd(&cnt[ei[EE + e]], 1);
}
__global__ void __launch_bounds__(SCB) k_scan1(const int* __restrict__ cnt,
                                               int* __restrict__ rowptr, int* __restrict__ bsum) {
    __shared__ int s[SCB];
    int b = blockIdx.x, t = threadIdx.x, i = b * SCB + t;
    int v = (i < NN) ? cnt[i] : 0;
    s[t] = v; __syncthreads();
    for (int off = 1; off < SCB; off <<= 1) {
        int add = (t >= off) ? s[t - off] : 0;
        __syncthreads();
        s[t] += add;
        __syncthreads();
    }
    if (i < NN) rowptr[i + 1] = s[t];
    if (t == SCB - 1) bsum[b] = s[t];
    if (b == 0 && t == 0) rowptr[0] = 0;
}
__global__ void __launch_bounds__(SCB) k_scan2(int* __restrict__ bsum) {
    __shared__ int s[SCB];
    int t = threadIdx.x;
    int v = (t < NB) ? bsum[t] : 0;
    s[t] = v; __syncthreads();
    for (int off = 1; off < SCB; off <<= 1) {
        int add = (t >= off) ? s[t - off] : 0;
        __syncthreads();
        s[t] += add;
        __syncthreads();
    }
    if (t < NB) bsum[t] = (t > 0) ? s[t - 1] : 0;
}
__global__ void __launch_bounds__(SCB) k_scan3(int* __restrict__ rowptr, const int* __restrict__ bsum) {
    int b = blockIdx.x, t = threadIdx.x, i = b * SCB + t;
    if (i < NN) rowptr[i + 1] += bsum[b];
}
__global__ void __launch_bounds__(256) k_fill(const int* __restrict__ ei,
                                              int* __restrict__ cursor, int* __restrict__ colx) {
    int e = blockIdx.x * 256 + threadIdx.x;
    if (e >= EE) return;
    int pos = atomicAdd(&cursor[ei[EE + e]], 1);
    colx[pos] = ei[e];
}

// ================= gather: agg[n] = sum_{e in CSR[n]} x[col[e]] =================
__global__ void __launch_bounds__(256) k_gather(const int* __restrict__ rowptr,
                                                const int* __restrict__ colx,
                                                const float* __restrict__ gx,
                                                float* __restrict__ gm) {
    int w = (blockIdx.x * 256 + threadIdx.x) >> 5;
    int lane = threadIdx.x & 31;
    if (w >= NN) return;
    int s = rowptr[w], e = rowptr[w + 1];
    const ull* X = (const ull*)gx;
    ull a0 = 0, a1 = 0, a2 = 0, a3 = 0;
    int i = s;
    for (; i + 3 < e; i += 4) {
        int c0 = colx[i], c1 = colx[i + 1], c2 = colx[i + 2], c3 = colx[i + 3];
        a0 = addf2(a0, X[(size_t)c0 * 32 + lane]);
        a1 = addf2(a1, X[(size_t)c1 * 32 + lane]);
        a2 = addf2(a2, X[(size_t)c2 * 32 + lane]);
        a3 = addf2(a3, X[(size_t)c3 * 32 + lane]);
    }
    for (; i < e; i++) a0 = addf2(a0, X[(size_t)colx[i] * 32 + lane]);
    a0 = addf2(addf2(a0, a1), addf2(a2, a3));
    ((ull*)gm)[(size_t)w * 32 + lane] = a0;
}

// ================= segment sum (pooling) =================
__global__ void __launch_bounds__(256) k_segsum(const float* __restrict__ src,
                                                float* __restrict__ dst,
                                                const int* __restrict__ map, int R) {
    long long t = (long long)blockIdx.x * 256 + threadIdx.x;
    int r = (int)(t >> 2);
    if (r >= R) return;
    int q = (int)(t & 3);
    int s = map[r];
    const float4* sp = (const float4*)(src + r * 64) + q * 4;
    float* dp = dst + s * 64 + q * 16;
#pragma unroll
    for (int i = 0; i < 4; i++) {
        float4 v = sp[i];
        asm volatile("red.global.add.v4.f32 [%0], {%1,%2,%3,%4};"
                     :: "l"(dp + i * 4), "f"(v.x), "f"(v.y), "f"(v.z), "f"(v.w)
                     : "memory");
    }
}

// ================= 2-layer MLP =================
__device__ __forceinline__ void zero_acc(ull acc[4][4]) {
#pragma unroll
    for (int i = 0; i < 4; i++)
#pragma unroll
        for (int j = 0; j < 4; j++) acc[i][j] = 0ULL;
}
__device__ __forceinline__ void load_wpack(ull* wp, const float* __restrict__ W,
                                           int ldw, int coff, int K2, int tid) {
    for (int idx = tid; idx < K2 * 64; idx += 256) {
        int kp = idx >> 6, j = idx & 63;
        wp[idx] = packf2(W[(2 * kp) * ldw + coff + j],
                         W[(2 * kp + 1) * ldw + coff + j]);
    }
}
template <int K2>
__device__ __forceinline__ void gemm_acc(const ull* __restrict__ in_s,
                                         const ull* __restrict__ wp_s,
                                         ull acc[4][4], int nt, int ct) {
#pragma unroll 8
    for (int kp = 0; kp < K2; kp++) {
        ulonglong2 w01 = *(const ulonglong2*)(wp_s + kp * 64 + ct * 4);
        ulonglong2 w23 = *(const ulonglong2*)(wp_s + kp * 64 + ct * 4 + 2);
#pragma unroll
        for (int i = 0; i < 4; i++) {
            ull a = in_s[(nt + 16 * i) * K2 + kp];
            acc[i][0] = ffma2(a, w01.x, acc[i][0]);
            acc[i][1] = ffma2(a, w01.y, acc[i][1]);
            acc[i][2] = ffma2(a, w23.x, acc[i][2]);
            acc[i][3] = ffma2(a, w23.y, acc[i][3]);
        }
    }
}
__global__ void __launch_bounds__(256) k_mlp(const float* __restrict__ in,
                                             float* __restrict__ out, int R,
                                             const float* __restrict__ W1,
                                             const float* __restrict__ b1,
                                             const float* __restrict__ W2,
                                             const float* __restrict__ b2) {
    extern __shared__ ull sm[];
    ull* in_s  = sm;
    ull* w1_s  = sm + 2048;
    ull* mid_s = sm + 4096;
    ull* w2_s  = sm + 6144;
    int tid = threadIdx.x;
    int row0 = blockIdx.x * 64;

    for (int idx = tid; idx < 1024; idx += 256) {
        int r = idx >> 4, c = idx & 15;
        int gr = row0 + r;
        float4 v = (gr < R) ? ((const float4*)in)[gr * 16 + c]
                            : make_float4(0.f, 0.f, 0.f, 0.f);
        ((float4*)in_s)[r * 16 + c] = v;
    }
    load_wpack(w1_s, W1, 64, 0, 32, tid);
    load_wpack(w2_s, W2, 64, 0, 32, tid);
    __syncthreads();

    int nt = tid >> 4, ct = tid & 15;
    ull acc[4][4];
    zero_acc(acc);
    gemm_acc<32>(in_s, w1_s, acc, nt, ct);
    float a0 = b1[ct * 4], a1 = b1[ct * 4 + 1], a2 = b1[ct * 4 + 2], a3 = b1[ct * 4 + 3];
#pragma unroll
    for (int i = 0; i < 4; i++) {
        int node = nt + 16 * i;
        float o0 = fmaxf(accred(acc[i][0]) + a0, 0.f);
        float o1 = fmaxf(accred(acc[i][1]) + a1, 0.f);
        float o2 = fmaxf(accred(acc[i][2]) + a2, 0.f);
        float o3 = fmaxf(accred(acc[i][3]) + a3, 0.f);
        mid_s[node * 32 + ct * 2]     = packf2(o0, o1);
        mid_s[node * 32 + ct * 2 + 1] = packf2(o2, o3);
    }
    __syncthreads();
    zero_acc(acc);
    gemm_acc<32>(mid_s, w2_s, acc, nt, ct);
    float c0b = b2[ct * 4], c1b = b2[ct * 4 + 1], c2b = b2[ct * 4 + 2], c3b = b2[ct * 4 + 3];
#pragma unroll
    for (int i = 0; i < 4; i++) {
        int gr = row0 + nt + 16 * i;
        if (gr < R)
            ((float4*)out)[gr * 16 + ct] = make_float4(
                accred(acc[i][0]) + c0b, accred(acc[i][1]) + c1b,
                accred(acc[i][2]) + c2b, accred(acc[i][3]) + c3b);
    }
}

// ================= final head =================
__device__ __forceinline__ float elu1(float v) { return v > 0.f ? v : expm1f(v); }

__global__ void k_final(const float* __restrict__ g,
                        const float* __restrict__ W1, const float* __restrict__ b1,
                        const float* __restrict__ W2, const float* __restrict__ b2,
                        const float* __restrict__ W3, const float* __restrict__ b3,
                        float* __restrict__ out) {
    int i = threadIdx.x;
    if (i >= NGR) return;
    float xr[64];
#pragma unroll
    for (int k = 0; k < 64; k++) xr[k] = g[i * 64 + k];
    float a1[32];
#pragma unroll
    for (int j = 0; j < 32; j++) {
        float s = b1[j];
#pragma unroll
        for (int k = 0; k < 64; k++) s += xr[k] * W1[k * 32 + j];
        a1[j] = elu1(s);
    }
    float a2[16];
#pragma unroll
    for (int j = 0; j < 16; j++) {
        float s = b2[j];
#pragma unroll
        for (int k = 0; k < 32; k++) s += a1[k] * W2[k * 16 + j];
        a2[j] = elu1(s);
    }
    float o = b3[0];
#pragma unroll
    for (int k = 0; k < 16; k++) o += a2[k] * W3[k];
    out[i] = o;
}

// ================= host launcher =================
extern "C" void kernel_launch(void* const* d_in, const int* in_sizes, int n_in,
                              void* d_out, int out_size) {
    (void)in_sizes; (void)n_in; (void)out_size;
    const int*   z       = (const int*)d_in[0];
    const int*   ei      = (const int*)d_in[1];
    const int*   n2s2    = (const int*)d_in[2];
    const int*   s22s    = (const int*)d_in[3];
    const int*   s2g     = (const int*)d_in[4];
    const float* z_emb   = (const float*)d_in[5];
    const float* trans_W = (const float*)d_in[6];
    const float* trans_b = (const float*)d_in[7];
    const float* conv_W  = (const float*)d_in[8];
    const float* Wih     = (const float*)d_in[9];
    const float* bih     = (const float*)d_in[10];
    const float* Whh     = (const float*)d_in[11];
    const float* bhh     = (const float*)d_in[12];
    const float* epW1 = (const float*)d_in[13]; const float* epb1 = (const float*)d_in[14];
    const float* epW2 = (const float*)d_in[15]; const float* epb2 = (const float*)d_in[16];
    const float* npW1 = (const float*)d_in[17]; const float* npb1 = (const float*)d_in[18];
    const float* npW2 = (const float*)d_in[19]; const float* npb2 = (const float*)d_in[20];
    const float* fc1W = (const float*)d_in[21]; const float* fc1b = (const float*)d_in[22];
    const float* fc2W = (const float*)d_in[23]; const float* fc2b = (const float*)d_in[24];
    const float* fc3W = (const float*)d_in[25]; const float* fc3b = (const float*)d_in[26];

    float *gx, *gm, *gwf, *gs2, *gs2b, *gs1, *gs1b, *gg;
    int *rowptr, *cursor, *colx, *bsum;
    cudaGetSymbolAddress((void**)&gx,     g_x);
    cudaGetSymbolAddress((void**)&gm,     g_m);
    cudaGetSymbolAddress((void**)&gwf,    g_wf);
    cudaGetSymbolAddress((void**)&gs2,    g_s2);
    cudaGetSymbolAddress((void**)&gs2b,   g_s2b);
    cudaGetSymbolAddress((void**)&gs1,    g_s1);
    cudaGetSymbolAddress((void**)&gs1b,   g_s1b);
    cudaGetSymbolAddress((void**)&gg,     g_gg);
    cudaGetSymbolAddress((void**)&rowptr, g_rowptr);
    cudaGetSymbolAddress((void**)&cursor, g_cursor);
    cudaGetSymbolAddress((void**)&colx,   g_colx);
    cudaGetSymbolAddress((void**)&bsum,   g_bsum);

    static int attr_done = 0;
    if (!attr_done) {
        cudaFuncSetAttribute(k_transform, cudaFuncAttributeMaxDynamicSharedMemorySize, 50176);
        cudaFuncSetAttribute(k_gru,       cudaFuncAttributeMaxDynamicSharedMemorySize, 182272);
        cudaFuncSetAttribute(k_mlp,       cudaFuncAttributeMaxDynamicSharedMemorySize, 65536);
        attr_done = 1;
    }

    // ---- weight fusion + CSR build (once per call) ----
    k_wfuse<<<(5 * 64 * 192 + 255) / 256, 256>>>(conv_W, Wih, gwf);
    cudaMemsetAsync(cursor, 0, (size_t)NN * 4);
    k_hist<<<(EE + 255) / 256, 256>>>(ei, cursor);
    k_scan1<<<NB, SCB>>>(cursor, rowptr, bsum);
    k_scan2<<<1, SCB>>>(bsum);
    k_scan3<<<NB, SCB>>>(rowptr, bsum);
    cudaMemcpyAsync(cursor, rowptr, (size_t)NN * 4, cudaMemcpyDeviceToDevice);
    k_fill<<<(EE + 255) / 256, 256>>>(ei, cursor, colx);

    const int GGRID = 148;
    int gath_blocks = (NN * 32 + 255) / 256;

    // layer 0
    k_embed<<<(NN * 16 + 255) / 256, 256>>>(z, z_emb, gx);
    k_gather<<<gath_blocks, 256>>>(rowptr, colx, gx, gm);
    k_gru<<<GGRID, 512, 182272>>>(gwf, bih, Whh, bhh, gx, gm);

    // layers 1..4
    for (int l = 1; l < 5; l++) {
        k_transform<<<4 * GGRID, 128, 50176>>>(z, z_emb + (size_t)l * 100 * 64,
                                               trans_W + (size_t)(l - 1) * 128 * 64,
                                               trans_b + (size_t)(l - 1) * 64, gx);
        k_gather<<<gath_blocks, 256>>>(rowptr, colx, gx, gm);
        k_gru<<<GGRID, 512, 182272>>>(gwf + (size_t)l * 12288, bih + (size_t)l * 192,
                                      Whh + (size_t)l * 64 * 192, bhh + (size_t)l * 192,
                                      gx, gm);
    }

    // pooling + MLPs
    cudaMemsetAsync(gs2, 0, (size_t)NSG2 * 64 * 4);
    k_segsum<<<(NN * 4 + 255) / 256, 256>>>(gx, gs2, n2s2, NN);
    k_mlp<<<(NSG2 + 63) / 64, 256, 65536>>>(gs2, gs2b, NSG2, epW1, epb1, epW2, epb2);

    cudaMemsetAsync(gs1, 0, (size_t)NSG * 64 * 4);
    k_segsum<<<(NSG2 * 4 + 255) / 256, 256>>>(gs2b, gs1, s22s, NSG2);
    k_mlp<<<(NSG + 63) / 64, 256, 65536>>>(gs1, gs1b, NSG, npW1, npb1, npW2, npb2);

    cudaMemsetAsync(gg, 0, (size_t)NGR * 64 * 4);
    k_segsum<<<(NSG * 4 + 255) / 256, 256>>>(gs1b, gg, s2g, NSG);

    k_final<<<1, 64>>>(gg, fc1W, fc1b, fc2W, fc2b, fc3W, fc3b, (float*)d_out);
}